// round 15
// baseline (speedup 1.0000x reference)
#include <cuda_runtime.h>
#include <cuda_fp16.h>
#include <cstdint>

// out[b,m,n] = round(alpha * sum_k A[b,m,k]*B[b,n,k]); B=64, M=N=1024, K=128.
// Inputs materialized int32, output f32, ptxas = sm_103 (no tcgen05).
//
// Round-15: pipelined chunks. 8 chunks x 8 batches. gemm_chunk_i computes
// chunk i (1024 tiles, 512 CTAs x 2 tiles = 1 wave) AND packs chunk i+1's
// int32 -> f16 data as a side duty (hidden under the write-bound compute;
// kernel boundary = sync). pack0 primes chunk 0. Stores use st.global.cs.

static constexpr int M_DIM = 1024;
static constexpr int N_DIM = 1024;
static constexpr int K_DIM = 128;
static constexpr int BATCH = 64;
static constexpr int NCHUNK = 8;
static constexpr int B_PER_CHUNK = BATCH / NCHUNK;          // 8
static constexpr int TILES_PER_CHUNK = 8 * 16 * B_PER_CHUNK; // 1024 (128x64 tiles)
static constexpr int GRID  = 512;                            // 2 tiles per CTA
static constexpr float ALPHA_CONST = 0.0078125f;

// groups of 16 int32 elems per tensor per chunk: 8*1024*128/16 = 65536 = GRID*128
static constexpr int GROUPS_PER_CHUNK = 65536;

static constexpr uint32_t SLOT_BYTES = 12288;   // A 8KB @0, B 4KB @8192
static constexpr uint32_t B_OFF      = 8192;
static constexpr uint32_t SMEM_TOTAL = 4 * SLOT_BYTES;   // 49152

__device__ __half g_ah[(size_t)BATCH * M_DIM * K_DIM];
__device__ __half g_bh[(size_t)BATCH * N_DIM * K_DIM];

__device__ __forceinline__ uint32_t h2pack(int x, int y) {
    __half2 h = __halves2half2(__int2half_rn(x), __int2half_rn(y));
    return *reinterpret_cast<uint32_t*>(&h);
}

// pack one 16-element group (index t) of both tensors: int32 -> f16
__device__ __forceinline__ void pack_group(const int4* __restrict__ A,
                                           const int4* __restrict__ B,
                                           size_t t) {
    int4 a[4], b[4];
    #pragma unroll
    for (int i = 0; i < 4; i++) { a[i] = A[t * 4 + i]; b[i] = B[t * 4 + i]; }
    uint4 ha0, ha1, hb0, hb1;
    ha0.x = h2pack(a[0].x, a[0].y); ha0.y = h2pack(a[0].z, a[0].w);
    ha0.z = h2pack(a[1].x, a[1].y); ha0.w = h2pack(a[1].z, a[1].w);
    ha1.x = h2pack(a[2].x, a[2].y); ha1.y = h2pack(a[2].z, a[2].w);
    ha1.z = h2pack(a[3].x, a[3].y); ha1.w = h2pack(a[3].z, a[3].w);
    hb0.x = h2pack(b[0].x, b[0].y); hb0.y = h2pack(b[0].z, b[0].w);
    hb0.z = h2pack(b[1].x, b[1].y); hb0.w = h2pack(b[1].z, b[1].w);
    hb1.x = h2pack(b[2].x, b[2].y); hb1.y = h2pack(b[2].z, b[2].w);
    hb1.z = h2pack(b[3].x, b[3].y); hb1.w = h2pack(b[3].z, b[3].w);
    reinterpret_cast<uint4*>(g_ah)[t * 2 + 0] = ha0;
    reinterpret_cast<uint4*>(g_ah)[t * 2 + 1] = ha1;
    reinterpret_cast<uint4*>(g_bh)[t * 2 + 0] = hb0;
    reinterpret_cast<uint4*>(g_bh)[t * 2 + 1] = hb1;
}

// ---------------- kernel 1: prime chunk 0 ----------------
__global__ __launch_bounds__(128)
void pack0_kernel(const int4* __restrict__ A, const int4* __restrict__ B) {
    pack_group(A, B, (size_t)blockIdx.x * 128 + threadIdx.x);
}

__device__ __forceinline__ void cp16(uint32_t dst, const void* src) {
    asm volatile("cp.async.cg.shared.global [%0], [%1], 16;"
                 :: "r"(dst), "l"(src) : "memory");
}

// ---------------- kernel 2: gemm chunk + pack next chunk ----------------
__global__ __launch_bounds__(128, 4)
void gemm_chunk_kernel(const float* __restrict__ alpha_p,
                       float* __restrict__ out,
                       const int4* __restrict__ A32,
                       const int4* __restrict__ B32,
                       int chunk)
{
    extern __shared__ int8_t smem[];   // 4 slots x 12KB

    const int tid  = threadIdx.x;
    const int warp = tid >> 5;
    const int lane = tid & 31;
    const int bid  = blockIdx.x;

    const float alpha = alpha_p ? *alpha_p : ALPHA_CONST;
    const uint32_t smemS = (uint32_t)__cvta_generic_to_shared(smem);

    const int mBase = (warp >> 1) * 64;   // warp row: 0 or 64
    const int nBase = (warp & 1) * 32;    // warp col: 0 or 32
    const int sub = lane >> 3;
    const int r8 = lane & 7;
    const int ld_row_off = ((sub & 1) << 3) + r8;
    const int ld_chunk   = sub >> 1;
    const int g  = lane >> 2;
    const int tq = lane & 3;

    const int tile_base = chunk * TILES_PER_CHUNK;

    auto load_stage = [&](int gs) {
        const int tl = bid + (gs >> 2) * GRID;
        if (tl < TILES_PER_CHUNK) {
            const int t = tile_base + tl;
            const int kc = gs & 3;
            const int bn = t & 15, bm = (t >> 4) & 7, bz = t >> 7;
            const int8_t* gA = reinterpret_cast<const int8_t*>(g_ah)
                + ((size_t)bz * M_DIM + (size_t)bm * 128) * (K_DIM * 2);
            const int8_t* gB = reinterpret_cast<const int8_t*>(g_bh)
                + ((size_t)bz * N_DIM + (size_t)bn * 64) * (K_DIM * 2);
            const uint32_t slot = smemS + (uint32_t)(gs & 3) * SLOT_BYTES;
            #pragma unroll
            for (int i = 0; i < 6; i++) {
                int idx = tid + i * 128;          // 0..767
                if (idx < 512) {                  // A slice: 128 rows x 64B
                    int row = idx >> 2;
                    int c   = idx & 3;
                    uint32_t soff = (uint32_t)row * 64
                                  + (uint32_t)((c ^ ((row >> 1) & 3)) << 4);
                    cp16(slot + soff,
                         gA + (size_t)row * 256 + (size_t)kc * 64 + (size_t)c * 16);
                } else {                           // B slice: 64 rows x 64B
                    int j   = idx - 512;
                    int row = j >> 2;
                    int c   = j & 3;
                    uint32_t soff = (uint32_t)row * 64
                                  + (uint32_t)((c ^ ((row >> 1) & 3)) << 4);
                    cp16(slot + B_OFF + soff,
                         gB + (size_t)row * 256 + (size_t)kc * 64 + (size_t)c * 16);
                }
            }
        }
        asm volatile("cp.async.commit_group;" ::: "memory");
    };

    // Prime the pipeline first (async), then do the pack side-duty so its
    // LDG latency overlaps the stage-0 wait.
    load_stage(0);
    load_stage(1);
    load_stage(2);

    if (chunk + 1 < NCHUNK) {
        size_t t = (size_t)(chunk + 1) * GROUPS_PER_CHUNK
                 + (size_t)bid * 128 + tid;
        pack_group(A32, B32, t);
    }

    const int total_stages = 8;   // 2 tiles x 4 k-stages
    float acc[4][4][4];

    for (int gs = 0; gs < total_stages; gs++) {
        asm volatile("cp.async.wait_group 2;" ::: "memory");
        __syncthreads();

        if ((gs & 3) == 0) {
            #pragma unroll
            for (int mi = 0; mi < 4; mi++)
                #pragma unroll
                for (int ni = 0; ni < 4; ni++)
                    #pragma unroll
                    for (int r = 0; r < 4; r++)
                        acc[mi][ni][r] = 0.0f;
        }

        const uint32_t slot = smemS + (uint32_t)(gs & 3) * SLOT_BYTES;

        #pragma unroll
        for (int kk2 = 0; kk2 < 2; kk2++) {       // 2 x k16 per stage
            const int c = kk2 * 2 + ld_chunk;

            uint32_t a[4][4];
            #pragma unroll
            for (int mi = 0; mi < 4; mi++) {
                int row = mBase + mi * 16 + ld_row_off;
                uint32_t addr = slot + (uint32_t)row * 64
                              + (uint32_t)((c ^ ((row >> 1) & 3)) << 4);
                asm volatile(
                    "ldmatrix.sync.aligned.m8n8.x4.shared.b16 {%0,%1,%2,%3}, [%4];"
                    : "=r"(a[mi][0]), "=r"(a[mi][1]), "=r"(a[mi][2]), "=r"(a[mi][3])
                    : "r"(addr));
            }
            uint32_t b[2][4];
            #pragma unroll
            for (int nj = 0; nj < 2; nj++) {
                int row = nBase + nj * 16 + ld_row_off;
                uint32_t addr = slot + B_OFF + (uint32_t)row * 64
                              + (uint32_t)((c ^ ((row >> 1) & 3)) << 4);
                asm volatile(
                    "ldmatrix.sync.aligned.m8n8.x4.shared.b16 {%0,%1,%2,%3}, [%4];"
                    : "=r"(b[nj][0]), "=r"(b[nj][1]), "=r"(b[nj][2]), "=r"(b[nj][3])
                    : "r"(addr));
            }
            #pragma unroll
            for (int mi = 0; mi < 4; mi++) {
                #pragma unroll
                for (int ni = 0; ni < 4; ni++) {
                    const int nj = ni >> 1;
                    const int up = ni & 1;
                    asm volatile(
                        "mma.sync.aligned.m16n8k16.row.col.f32.f16.f16.f32 "
                        "{%0,%1,%2,%3}, {%4,%5,%6,%7}, {%8,%9}, {%0,%1,%2,%3};"
                        : "+f"(acc[mi][ni][0]), "+f"(acc[mi][ni][1]),
                          "+f"(acc[mi][ni][2]), "+f"(acc[mi][ni][3])
                        : "r"(a[mi][0]), "r"(a[mi][1]), "r"(a[mi][2]), "r"(a[mi][3]),
                          "r"(b[nj][up]), "r"(b[nj][up + 2]));
                }
            }
        }

        load_stage(gs + 3);

        if ((gs & 3) == 3) {
            const int t = tile_base + bid + (gs >> 2) * GRID;
            const int bn = t & 15, bm = (t >> 4) & 7, bz = t >> 7;
            float* gOut = out + ((size_t)bz * M_DIM + (size_t)bm * 128) * N_DIM
                              + (size_t)bn * 64;
            #pragma unroll
            for (int mi = 0; mi < 4; mi++) {
                #pragma unroll
                for (int ni = 0; ni < 4; ni++) {
                    int r0 = mBase + mi * 16 + g;
                    int c2 = nBase + ni * 8 + tq * 2;
                    float* p0 = gOut + (size_t)r0 * N_DIM + c2;
                    float* p1 = gOut + (size_t)(r0 + 8) * N_DIM + c2;
                    float x0 = rintf(acc[mi][ni][0] * alpha);
                    float y0 = rintf(acc[mi][ni][1] * alpha);
                    float x1 = rintf(acc[mi][ni][2] * alpha);
                    float y1 = rintf(acc[mi][ni][3] * alpha);
                    asm volatile("st.global.cs.v2.f32 [%0], {%1, %2};"
                                 :: "l"(p0), "f"(x0), "f"(y0) : "memory");
                    asm volatile("st.global.cs.v2.f32 [%0], {%1, %2};"
                                 :: "l"(p1), "f"(x1), "f"(y1) : "memory");
                }
            }
        }
    }
}

extern "C" void kernel_launch(void* const* d_in, const int* in_sizes, int n_in,
                              void* d_out, int out_size) {
    int i_alpha = -1;
    for (int i = 0; i < n_in; i++)
        if (in_sizes[i] == 1) { i_alpha = i; break; }
    int big[2] = {-1, -1};
    int nb = 0;
    for (int i = 0; i < n_in && nb < 2; i++)
        if (i != i_alpha) big[nb++] = i;
    if (nb < 2) return;

    const int4*  a     = (const int4*)d_in[big[0]];
    const int4*  b     = (const int4*)d_in[big[1]];
    const float* alpha = (i_alpha >= 0) ? (const float*)d_in[i_alpha] : nullptr;
    float*       out   = (float*)d_out;

    static bool attr_set = false;
    if (!attr_set) {
        cudaFuncSetAttribute(gemm_chunk_kernel,
                             cudaFuncAttributeMaxDynamicSharedMemorySize, SMEM_TOTAL);
        attr_set = true;
    }

    pack0_kernel<<<GRID, 128>>>(a, b);    // prime chunk 0
    for (int c = 0; c < NCHUNK; c++)
        gemm_chunk_kernel<<<GRID, 128, SMEM_TOTAL>>>(alpha, out, a, b, c);
}

// round 16
// speedup vs baseline: 1.3208x; 1.3208x over previous
#include <cuda_runtime.h>
#include <cuda_fp16.h>
#include <cstdint>

// out[b,m,n] = round(alpha * sum_k A[b,m,k]*B[b,n,k]); B=64, M=N=1024, K=128.
// Inputs materialized int32, output f32, ptxas = sm_103 (no tcgen05).
//
// Round-16: occupancy + barrier attack. Evidence: all pipes <=70%, issue 33%,
// occ 23% across 4 structurally different kernels pinned at ~83us => latency
// bound. Changes: warp tile 32x32 (acc 32 regs) + launch_bounds(256,3)
// => 24 warps/SM; k64 stages with ONE __syncthreads per stage (2/tile).

static constexpr int M_DIM = 1024;
static constexpr int N_DIM = 1024;
static constexpr int K_DIM = 128;
static constexpr int BATCH = 64;
static constexpr int TILES = 8 * 16 * BATCH;  // 8192 tiles of 128x64
static constexpr int GRID  = 456;             // 3 CTAs/SM on 152 SMs
static constexpr float ALPHA_CONST = 0.0078125f;

static constexpr uint32_t SLOT_BYTES = 24576;   // A 16KB @0, B 8KB @16384
static constexpr uint32_t B_OFF      = 16384;
static constexpr uint32_t SMEM_TOTAL = 2 * SLOT_BYTES;   // 49152

__device__ __half g_ah[(size_t)BATCH * M_DIM * K_DIM];
__device__ __half g_bh[(size_t)BATCH * N_DIM * K_DIM];

__device__ __forceinline__ uint32_t h2pack(int x, int y) {
    __half2 h = __halves2half2(__int2half_rn(x), __int2half_rn(y));
    return *reinterpret_cast<uint32_t*>(&h);
}

// ---------------- kernel 1: int32 -> f16 pack ----------------
__global__ __launch_bounds__(256)
void pack_kernel(const int4* __restrict__ A, const int4* __restrict__ B) {
    size_t t = (size_t)blockIdx.x * 256 + threadIdx.x;   // one 16-value group
    int4 a[4], b[4];
    #pragma unroll
    for (int i = 0; i < 4; i++) { a[i] = A[t * 4 + i]; b[i] = B[t * 4 + i]; }
    uint4 ha0, ha1, hb0, hb1;
    ha0.x = h2pack(a[0].x, a[0].y); ha0.y = h2pack(a[0].z, a[0].w);
    ha0.z = h2pack(a[1].x, a[1].y); ha0.w = h2pack(a[1].z, a[1].w);
    ha1.x = h2pack(a[2].x, a[2].y); ha1.y = h2pack(a[2].z, a[2].w);
    ha1.z = h2pack(a[3].x, a[3].y); ha1.w = h2pack(a[3].z, a[3].w);
    hb0.x = h2pack(b[0].x, b[0].y); hb0.y = h2pack(b[0].z, b[0].w);
    hb0.z = h2pack(b[1].x, b[1].y); hb0.w = h2pack(b[1].z, b[1].w);
    hb1.x = h2pack(b[2].x, b[2].y); hb1.y = h2pack(b[2].z, b[2].w);
    hb1.z = h2pack(b[3].x, b[3].y); hb1.w = h2pack(b[3].z, b[3].w);
    reinterpret_cast<uint4*>(g_ah)[t * 2 + 0] = ha0;
    reinterpret_cast<uint4*>(g_ah)[t * 2 + 1] = ha1;
    reinterpret_cast<uint4*>(g_bh)[t * 2 + 0] = hb0;
    reinterpret_cast<uint4*>(g_bh)[t * 2 + 1] = hb1;
}

__device__ __forceinline__ void cp16(uint32_t dst, const void* src) {
    asm volatile("cp.async.cg.shared.global [%0], [%1], 16;"
                 :: "r"(dst), "l"(src) : "memory");
}

// ---------------- kernel 2: high-occupancy pipelined HMMA GEMM ----------------
// Tile map: bn = t & 15 (64-wide), bm = (t>>4) & 7 (128-tall), bz = t >> 7.
// Stage = k64 half-tile: A 128rows x 128B, B 64rows x 128B.
__global__ __launch_bounds__(256, 3)
void gemm_hmma_kernel(const float* __restrict__ alpha_p,
                      float* __restrict__ out)
{
    extern __shared__ int8_t smem[];   // 2 slots x 24KB

    const int tid  = threadIdx.x;
    const int warp = tid >> 5;         // 0..7
    const int lane = tid & 31;
    const int bid  = blockIdx.x;

    const float alpha = alpha_p ? *alpha_p : ALPHA_CONST;
    const uint32_t smemS = (uint32_t)__cvta_generic_to_shared(smem);

    const int mBase = (warp >> 1) * 32;   // 0,32,64,96
    const int nBase = (warp & 1) * 32;    // 0,32
    const int sub = lane >> 3;
    const int r8 = lane & 7;
    const int ld_row_off = ((sub & 1) << 3) + r8;   // row within 16-row group
    const int ld_chunk   = sub >> 1;      // 0/1: which 16B within a k16 step
    const int g  = lane >> 2;
    const int tq = lane & 3;

    // Load k64 stage gs: tile = bid + (gs>>1)*GRID, half kh = gs&1.
    // A: 1024 chunks, B: 512 chunks; 256 threads x 6. Always commits.
    auto load_stage = [&](int gs) {
        const int t = bid + (gs >> 1) * GRID;
        if (t < TILES) {
            const int kh = gs & 1;
            const int bn = t & 15, bm = (t >> 4) & 7, bz = t >> 7;
            const int8_t* gA = reinterpret_cast<const int8_t*>(g_ah)
                + ((size_t)bz * M_DIM + (size_t)bm * 128) * (K_DIM * 2)
                + (size_t)kh * 128;
            const int8_t* gB = reinterpret_cast<const int8_t*>(g_bh)
                + ((size_t)bz * N_DIM + (size_t)bn * 64) * (K_DIM * 2)
                + (size_t)kh * 128;
            const uint32_t slot = smemS + (uint32_t)(gs & 1) * SLOT_BYTES;
            #pragma unroll
            for (int i = 0; i < 6; i++) {
                int idx = tid + i * 256;          // 0..1535
                if (idx < 1024) {                 // A: row = idx>>3, c = idx&7
                    int row = idx >> 3;
                    int c   = idx & 7;
                    uint32_t soff = (uint32_t)row * 128
                                  + (uint32_t)((c ^ (row & 7)) << 4);
                    cp16(slot + soff, gA + (size_t)row * 256 + (size_t)c * 16);
                } else {                           // B
                    int j   = idx - 1024;
                    int row = j >> 3;
                    int c   = j & 7;
                    uint32_t soff = (uint32_t)row * 128
                                  + (uint32_t)((c ^ (row & 7)) << 4);
                    cp16(slot + B_OFF + soff, gB + (size_t)row * 256 + (size_t)c * 16);
                }
            }
        }
        asm volatile("cp.async.commit_group;" ::: "memory");
    };

    const int ntiles = (TILES - bid + GRID - 1) / GRID;
    const int total_stages = ntiles * 2;

    load_stage(0);

    float acc[2][4][4];

    for (int gs = 0; gs < total_stages; gs++) {
        asm volatile("cp.async.wait_group 0;" ::: "memory");
        __syncthreads();   // stage gs visible; all warps past stage gs-1

        load_stage(gs + 1);   // other slot: reads finished at stage gs-1

        if ((gs & 1) == 0) {
            #pragma unroll
            for (int mi = 0; mi < 2; mi++)
                #pragma unroll
                for (int ni = 0; ni < 4; ni++)
                    #pragma unroll
                    for (int r = 0; r < 4; r++)
                        acc[mi][ni][r] = 0.0f;
        }

        const uint32_t slot = smemS + (uint32_t)(gs & 1) * SLOT_BYTES;

        #pragma unroll
        for (int kk = 0; kk < 4; kk++) {          // 4 x k16 per k64 stage
            const int c = kk * 2 + ld_chunk;

            uint32_t a[2][4];
            #pragma unroll
            for (int mi = 0; mi < 2; mi++) {
                int row = mBase + mi * 16 + ld_row_off;
                uint32_t addr = slot + (uint32_t)row * 128
                              + (uint32_t)((c ^ (row & 7)) << 4);
                asm volatile(
                    "ldmatrix.sync.aligned.m8n8.x4.shared.b16 {%0,%1,%2,%3}, [%4];"
                    : "=r"(a[mi][0]), "=r"(a[mi][1]), "=r"(a[mi][2]), "=r"(a[mi][3])
                    : "r"(addr));
            }
            uint32_t b[2][4];
            #pragma unroll
            for (int nj = 0; nj < 2; nj++) {
                int row = nBase + nj * 16 + ld_row_off;
                uint32_t addr = slot + B_OFF + (uint32_t)row * 128
                              + (uint32_t)((c ^ (row & 7)) << 4);
                asm volatile(
                    "ldmatrix.sync.aligned.m8n8.x4.shared.b16 {%0,%1,%2,%3}, [%4];"
                    : "=r"(b[nj][0]), "=r"(b[nj][1]), "=r"(b[nj][2]), "=r"(b[nj][3])
                    : "r"(addr));
            }
            #pragma unroll
            for (int mi = 0; mi < 2; mi++) {
                #pragma unroll
                for (int ni = 0; ni < 4; ni++) {
                    const int nj = ni >> 1;
                    const int up = ni & 1;
                    asm volatile(
                        "mma.sync.aligned.m16n8k16.row.col.f32.f16.f16.f32 "
                        "{%0,%1,%2,%3}, {%4,%5,%6,%7}, {%8,%9}, {%0,%1,%2,%3};"
                        : "+f"(acc[mi][ni][0]), "+f"(acc[mi][ni][1]),
                          "+f"(acc[mi][ni][2]), "+f"(acc[mi][ni][3])
                        : "r"(a[mi][0]), "r"(a[mi][1]), "r"(a[mi][2]), "r"(a[mi][3]),
                          "r"(b[nj][up]), "r"(b[nj][up + 2]));
                }
            }
        }

        if ((gs & 1) == 1) {
            const int t = bid + (gs >> 1) * GRID;
            const int bn = t & 15, bm = (t >> 4) & 7, bz = t >> 7;
            float* gOut = out + ((size_t)bz * M_DIM + (size_t)bm * 128) * N_DIM
                              + (size_t)bn * 64;
            #pragma unroll
            for (int mi = 0; mi < 2; mi++) {
                #pragma unroll
                for (int ni = 0; ni < 4; ni++) {
                    int r0 = mBase + mi * 16 + g;
                    int c2 = nBase + ni * 8 + tq * 2;
                    float2 v0, v1;
                    v0.x = rintf(acc[mi][ni][0] * alpha);
                    v0.y = rintf(acc[mi][ni][1] * alpha);
                    v1.x = rintf(acc[mi][ni][2] * alpha);
                    v1.y = rintf(acc[mi][ni][3] * alpha);
                    *reinterpret_cast<float2*>(gOut + (size_t)r0 * N_DIM + c2)       = v0;
                    *reinterpret_cast<float2*>(gOut + (size_t)(r0 + 8) * N_DIM + c2) = v1;
                }
            }
        }
    }
}

extern "C" void kernel_launch(void* const* d_in, const int* in_sizes, int n_in,
                              void* d_out, int out_size) {
    int i_alpha = -1;
    for (int i = 0; i < n_in; i++)
        if (in_sizes[i] == 1) { i_alpha = i; break; }
    int big[2] = {-1, -1};
    int nb = 0;
    for (int i = 0; i < n_in && nb < 2; i++)
        if (i != i_alpha) big[nb++] = i;
    if (nb < 2) return;

    const int4*  a     = (const int4*)d_in[big[0]];
    const int4*  b     = (const int4*)d_in[big[1]];
    const float* alpha = (i_alpha >= 0) ? (const float*)d_in[i_alpha] : nullptr;
    float*       out   = (float*)d_out;

    static bool attr_set = false;
    if (!attr_set) {
        cudaFuncSetAttribute(gemm_hmma_kernel,
                             cudaFuncAttributeMaxDynamicSharedMemorySize, SMEM_TOTAL);
        attr_set = true;
    }

    pack_kernel<<<2048, 256>>>(a, b);                        // int32 -> f16
    gemm_hmma_kernel<<<GRID, 256, SMEM_TOTAL>>>(alpha, out); // 24-warp/SM GEMM
}

// round 17
// speedup vs baseline: 1.3221x; 1.0010x over previous
#include <cuda_runtime.h>
#include <cuda_fp16.h>
#include <cstdint>

// out[b,m,n] = round(alpha * sum_k A[b,m,k]*B[b,n,k]); B=64, M=N=1024, K=128.
// Inputs materialized int32, output f32, ptxas = sm_103 (no tcgen05).
//
// Round-17: intra-warp fragment double-buffering. Evidence: 5 kernels pinned
// at 80-84us with all pipes <=77% -> exposed LDSM->HMMA chains. Now ldmatrix
// for k-step kk+1 issues before the mmas of step kk (latency hidden under
// ~64cyc of HMMA). CTA = 128 thr / 4 warps / 64x64 tile, launch_bounds(128,5)
// (reg cap 102 fits acc32 + 2x16 frag regs), 20 warps/SM.

static constexpr int M_DIM = 1024;
static constexpr int N_DIM = 1024;
static constexpr int K_DIM = 128;
static constexpr int BATCH = 64;
static constexpr int TILES = 16 * 16 * BATCH;  // 16384 tiles of 64x64
static constexpr int GRID  = 760;              // 5 CTAs/SM on 152 SMs
static constexpr float ALPHA_CONST = 0.0078125f;

static constexpr uint32_t SLOT_BYTES = 16384;   // A 8KB @0, B 8KB @8192
static constexpr uint32_t B_OFF      = 8192;
static constexpr uint32_t SMEM_TOTAL = 2 * SLOT_BYTES;   // 32768

__device__ __half g_ah[(size_t)BATCH * M_DIM * K_DIM];
__device__ __half g_bh[(size_t)BATCH * N_DIM * K_DIM];

__device__ __forceinline__ uint32_t h2pack(int x, int y) {
    __half2 h = __halves2half2(__int2half_rn(x), __int2half_rn(y));
    return *reinterpret_cast<uint32_t*>(&h);
}

// ---------------- kernel 1: int32 -> f16 pack ----------------
__global__ __launch_bounds__(256)
void pack_kernel(const int4* __restrict__ A, const int4* __restrict__ B) {
    size_t t = (size_t)blockIdx.x * 256 + threadIdx.x;   // one 16-value group
    int4 a[4], b[4];
    #pragma unroll
    for (int i = 0; i < 4; i++) { a[i] = A[t * 4 + i]; b[i] = B[t * 4 + i]; }
    uint4 ha0, ha1, hb0, hb1;
    ha0.x = h2pack(a[0].x, a[0].y); ha0.y = h2pack(a[0].z, a[0].w);
    ha0.z = h2pack(a[1].x, a[1].y); ha0.w = h2pack(a[1].z, a[1].w);
    ha1.x = h2pack(a[2].x, a[2].y); ha1.y = h2pack(a[2].z, a[2].w);
    ha1.z = h2pack(a[3].x, a[3].y); ha1.w = h2pack(a[3].z, a[3].w);
    hb0.x = h2pack(b[0].x, b[0].y); hb0.y = h2pack(b[0].z, b[0].w);
    hb0.z = h2pack(b[1].x, b[1].y); hb0.w = h2pack(b[1].z, b[1].w);
    hb1.x = h2pack(b[2].x, b[2].y); hb1.y = h2pack(b[2].z, b[2].w);
    hb1.z = h2pack(b[3].x, b[3].y); hb1.w = h2pack(b[3].z, b[3].w);
    reinterpret_cast<uint4*>(g_ah)[t * 2 + 0] = ha0;
    reinterpret_cast<uint4*>(g_ah)[t * 2 + 1] = ha1;
    reinterpret_cast<uint4*>(g_bh)[t * 2 + 0] = hb0;
    reinterpret_cast<uint4*>(g_bh)[t * 2 + 1] = hb1;
}

__device__ __forceinline__ void cp16(uint32_t dst, const void* src) {
    asm volatile("cp.async.cg.shared.global [%0], [%1], 16;"
                 :: "r"(dst), "l"(src) : "memory");
}

// ---------------- kernel 2: frag-pipelined HMMA GEMM ----------------
// Tile map: bn = t & 15 (64-wide), bm = (t>>4) & 15 (64-tall), bz = t >> 8.
// Stage = k64 half: A 64rows x 128B, B 64rows x 128B.
__global__ __launch_bounds__(128, 5)
void gemm_hmma_kernel(const float* __restrict__ alpha_p,
                      float* __restrict__ out)
{
    extern __shared__ int8_t smem[];   // 2 slots x 16KB

    const int tid  = threadIdx.x;
    const int warp = tid >> 5;         // 0..3
    const int lane = tid & 31;
    const int bid  = blockIdx.x;

    const float alpha = alpha_p ? *alpha_p : ALPHA_CONST;
    const uint32_t smemS = (uint32_t)__cvta_generic_to_shared(smem);

    const int mBase = (warp >> 1) * 32;   // 0,32
    const int nBase = (warp & 1) * 32;    // 0,32
    const int sub = lane >> 3;
    const int r8 = lane & 7;
    const int ld_row_off = ((sub & 1) << 3) + r8;   // row within 16-row group
    const int ld_chunk   = sub >> 1;      // 0/1: which 16B within a k16 step
    const int g  = lane >> 2;
    const int tq = lane & 3;

    // Load k64 stage gs: tile = bid + (gs>>1)*GRID, half kh = gs&1.
    // A: 512 chunks, B: 512 chunks; 128 threads x 8. Always commits.
    auto load_stage = [&](int gs) {
        const int t = bid + (gs >> 1) * GRID;
        if (t < TILES) {
            const int kh = gs & 1;
            const int bn = t & 15, bm = (t >> 4) & 15, bz = t >> 8;
            const int8_t* gA = reinterpret_cast<const int8_t*>(g_ah)
                + ((size_t)bz * M_DIM + (size_t)bm * 64) * (K_DIM * 2)
                + (size_t)kh * 128;
            const int8_t* gB = reinterpret_cast<const int8_t*>(g_bh)
                + ((size_t)bz * N_DIM + (size_t)bn * 64) * (K_DIM * 2)
                + (size_t)kh * 128;
            const uint32_t slot = smemS + (uint32_t)(gs & 1) * SLOT_BYTES;
            #pragma unroll
            for (int i = 0; i < 8; i++) {
                int idx = tid + i * 128;          // 0..1023
                int row = (idx >> 3) & 63;
                int c   = idx & 7;
                uint32_t soff = (uint32_t)row * 128
                              + (uint32_t)((c ^ (row & 7)) << 4);
                if (idx < 512)
                    cp16(slot + soff, gA + (size_t)row * 256 + (size_t)c * 16);
                else
                    cp16(slot + B_OFF + soff, gB + (size_t)row * 256 + (size_t)c * 16);
            }
        }
        asm volatile("cp.async.commit_group;" ::: "memory");
    };

    // Fragment load for k16 step kk (0..3) of the current slot into buffer fb.
    uint32_t af[2][2][4], bf[2][2][4];
    auto load_frags = [&](uint32_t slot, int kk, int fb) {
        const int c = kk * 2 + ld_chunk;
        #pragma unroll
        for (int mi = 0; mi < 2; mi++) {
            int row = mBase + mi * 16 + ld_row_off;
            uint32_t addr = slot + (uint32_t)row * 128
                          + (uint32_t)((c ^ (row & 7)) << 4);
            asm volatile(
                "ldmatrix.sync.aligned.m8n8.x4.shared.b16 {%0,%1,%2,%3}, [%4];"
                : "=r"(af[fb][mi][0]), "=r"(af[fb][mi][1]),
                  "=r"(af[fb][mi][2]), "=r"(af[fb][mi][3])
                : "r"(addr));
        }
        #pragma unroll
        for (int nj = 0; nj < 2; nj++) {
            int row = nBase + nj * 16 + ld_row_off;
            uint32_t addr = slot + B_OFF + (uint32_t)row * 128
                          + (uint32_t)((c ^ (row & 7)) << 4);
            asm volatile(
                "ldmatrix.sync.aligned.m8n8.x4.shared.b16 {%0,%1,%2,%3}, [%4];"
                : "=r"(bf[fb][nj][0]), "=r"(bf[fb][nj][1]),
                  "=r"(bf[fb][nj][2]), "=r"(bf[fb][nj][3])
                : "r"(addr));
        }
    };

    const int ntiles = (TILES - bid + GRID - 1) / GRID;
    const int total_stages = ntiles * 2;

    load_stage(0);

    float acc[2][4][4];

    for (int gs = 0; gs < total_stages; gs++) {
        asm volatile("cp.async.wait_group 0;" ::: "memory");
        __syncthreads();   // stage gs visible; all warps past stage gs-1

        load_stage(gs + 1);   // other slot: its reads finished at stage gs-1

        if ((gs & 1) == 0) {
            #pragma unroll
            for (int mi = 0; mi < 2; mi++)
                #pragma unroll
                for (int ni = 0; ni < 4; ni++)
                    #pragma unroll
                    for (int r = 0; r < 4; r++)
                        acc[mi][ni][r] = 0.0f;
        }

        const uint32_t slot = smemS + (uint32_t)(gs & 1) * SLOT_BYTES;

        // Fragment-pipelined k loop: load kk+1 while mma'ing kk.
        load_frags(slot, 0, 0);
        #pragma unroll
        for (int kk = 0; kk < 4; kk++) {
            const int cur = kk & 1;
            if (kk < 3) load_frags(slot, kk + 1, cur ^ 1);
            #pragma unroll
            for (int mi = 0; mi < 2; mi++) {
                #pragma unroll
                for (int ni = 0; ni < 4; ni++) {
                    const int nj = ni >> 1;
                    const int up = ni & 1;
                    asm volatile(
                        "mma.sync.aligned.m16n8k16.row.col.f32.f16.f16.f32 "
                        "{%0,%1,%2,%3}, {%4,%5,%6,%7}, {%8,%9}, {%0,%1,%2,%3};"
                        : "+f"(acc[mi][ni][0]), "+f"(acc[mi][ni][1]),
                          "+f"(acc[mi][ni][2]), "+f"(acc[mi][ni][3])
                        : "r"(af[cur][mi][0]), "r"(af[cur][mi][1]),
                          "r"(af[cur][mi][2]), "r"(af[cur][mi][3]),
                          "r"(bf[cur][nj][up]), "r"(bf[cur][nj][up + 2]));
                }
            }
        }

        if ((gs & 1) == 1) {
            const int t = bid + (gs >> 1) * GRID;
            const int bn = t & 15, bm = (t >> 4) & 15, bz = t >> 8;
            float* gOut = out + ((size_t)bz * M_DIM + (size_t)bm * 64) * N_DIM
                              + (size_t)bn * 64;
            #pragma unroll
            for (int mi = 0; mi < 2; mi++) {
                #pragma unroll
                for (int ni = 0; ni < 4; ni++) {
                    int r0 = mBase + mi * 16 + g;
                    int c2 = nBase + ni * 8 + tq * 2;
                    float2 v0, v1;
                    v0.x = rintf(acc[mi][ni][0] * alpha);
                    v0.y = rintf(acc[mi][ni][1] * alpha);
                    v1.x = rintf(acc[mi][ni][2] * alpha);
                    v1.y = rintf(acc[mi][ni][3] * alpha);
                    *reinterpret_cast<float2*>(gOut + (size_t)r0 * N_DIM + c2)       = v0;
                    *reinterpret_cast<float2*>(gOut + (size_t)(r0 + 8) * N_DIM + c2) = v1;
                }
            }
        }
    }
}

extern "C" void kernel_launch(void* const* d_in, const int* in_sizes, int n_in,
                              void* d_out, int out_size) {
    int i_alpha = -1;
    for (int i = 0; i < n_in; i++)
        if (in_sizes[i] == 1) { i_alpha = i; break; }
    int big[2] = {-1, -1};
    int nb = 0;
    for (int i = 0; i < n_in && nb < 2; i++)
        if (i != i_alpha) big[nb++] = i;
    if (nb < 2) return;

    const int4*  a     = (const int4*)d_in[big[0]];
    const int4*  b     = (const int4*)d_in[big[1]];
    const float* alpha = (i_alpha >= 0) ? (const float*)d_in[i_alpha] : nullptr;
    float*       out   = (float*)d_out;

    static bool attr_set = false;
    if (!attr_set) {
        cudaFuncSetAttribute(gemm_hmma_kernel,
                             cudaFuncAttributeMaxDynamicSharedMemorySize, SMEM_TOTAL);
        attr_set = true;
    }

    pack_kernel<<<2048, 256>>>(a, b);                        // int32 -> f16
    gemm_hmma_kernel<<<GRID, 128, SMEM_TOTAL>>>(alpha, out); // frag-pipelined
}